// round 1
// baseline (speedup 1.0000x reference)
#include <cuda_runtime.h>
#include <math.h>

#define N_NODES 100000
#define N_EDGES 1600000

// scratch (static device arrays; no allocation at runtime)
__device__ float g_dot[N_EDGES];
__device__ float g_m[N_NODES];
__device__ float g_s[N_NODES];

struct SW {
    float W1[4][3][16];
    float b1[4][16], g1[4][16], be1[4][16];
    float W2[4][16][16];
    float b2[4][16], g2[4][16], be2[4][16];
    float W3a[3][16][4];   // W3_00, W3_01, W3_10
    float b3a[3][4];
    float W3_11[16][12];
    float b3_11[12];
    float wq[8];           // [2][2][2]
};

__device__ __forceinline__ void ln_relu(float* h, const float* g, const float* be) {
    float s = 0.f;
#pragma unroll
    for (int j = 0; j < 16; j++) s += h[j];
    float mu = s * (1.f / 16.f);
    float vs = 0.f;
#pragma unroll
    for (int j = 0; j < 16; j++) { float d = h[j] - mu; vs = fmaf(d, d, vs); }
    float inv = rsqrtf(vs * (1.f / 16.f) + 1e-5f);
#pragma unroll
    for (int j = 0; j < 16; j++) {
        float val = fmaf((h[j] - mu) * inv, g[j], be[j]);
        h[j] = fmaxf(val, 0.f);
    }
}

template <int OUT>
__device__ __forceinline__ void radial(const SW& sw, int i, const float* W3, const float* b3,
                                       float v0, float v1, float v2, float* R) {
    float h[16];
#pragma unroll
    for (int j = 0; j < 16; j++)
        h[j] = fmaf(v0, sw.W1[i][0][j],
               fmaf(v1, sw.W1[i][1][j],
               fmaf(v2, sw.W1[i][2][j], sw.b1[i][j])));
    ln_relu(h, sw.g1[i], sw.be1[i]);
    float h2[16];
#pragma unroll
    for (int j = 0; j < 16; j++) {
        float acc = sw.b2[i][j];
#pragma unroll
        for (int k = 0; k < 16; k++) acc = fmaf(h[k], sw.W2[i][k][j], acc);
        h2[j] = acc;
    }
    ln_relu(h2, sw.g2[i], sw.be2[i]);
#pragma unroll
    for (int o = 0; o < OUT; o++) {
        float acc = b3[o];
#pragma unroll
        for (int k = 0; k < 16; k++) acc = fmaf(h2[k], W3[k * OUT + o], acc);
        R[o] = acc;
    }
}

__device__ __forceinline__ void atomicMaxF(float* addr, float val) {
    if (val >= 0.f) atomicMax((int*)addr, __float_as_int(val));
    else            atomicMin((unsigned int*)addr, __float_as_uint(val));
}

__global__ void init_kernel() {
    int n = blockIdx.x * blockDim.x + threadIdx.x;
    if (n < N_NODES) {
        g_m[n] = -INFINITY;
        g_s[n] = 0.f;
    }
}

__global__ __launch_bounds__(256) void edge_kernel(
    const float* __restrict__ f0, const float* __restrict__ f1,
    const float* __restrict__ dist,
    const int* __restrict__ u, const int* __restrict__ v,
    const float* __restrict__ wq,
    const float* __restrict__ wj00, const float* __restrict__ wj01,
    const float* __restrict__ wj10, const float* __restrict__ wj11,
    const float* __restrict__ rW1, const float* __restrict__ rb1,
    const float* __restrict__ g1, const float* __restrict__ be1,
    const float* __restrict__ rW2, const float* __restrict__ rb2,
    const float* __restrict__ g2, const float* __restrict__ be2,
    const float* __restrict__ W3_00, const float* __restrict__ b3_00,
    const float* __restrict__ W3_01, const float* __restrict__ b3_01,
    const float* __restrict__ W3_10, const float* __restrict__ b3_10,
    const float* __restrict__ W3_11, const float* __restrict__ b3_11)
{
    __shared__ SW sw;
    {
        int t = threadIdx.x;
        for (int i = t; i < 192;  i += blockDim.x) ((float*)sw.W1)[i]  = rW1[i];
        for (int i = t; i < 64;   i += blockDim.x) ((float*)sw.b1)[i]  = rb1[i];
        for (int i = t; i < 64;   i += blockDim.x) ((float*)sw.g1)[i]  = g1[i];
        for (int i = t; i < 64;   i += blockDim.x) ((float*)sw.be1)[i] = be1[i];
        for (int i = t; i < 1024; i += blockDim.x) ((float*)sw.W2)[i]  = rW2[i];
        for (int i = t; i < 64;   i += blockDim.x) ((float*)sw.b2)[i]  = rb2[i];
        for (int i = t; i < 64;   i += blockDim.x) ((float*)sw.g2)[i]  = g2[i];
        for (int i = t; i < 64;   i += blockDim.x) ((float*)sw.be2)[i] = be2[i];
        for (int i = t; i < 64;   i += blockDim.x) ((float*)sw.W3a[0])[i] = W3_00[i];
        for (int i = t; i < 64;   i += blockDim.x) ((float*)sw.W3a[1])[i] = W3_01[i];
        for (int i = t; i < 64;   i += blockDim.x) ((float*)sw.W3a[2])[i] = W3_10[i];
        for (int i = t; i < 4;    i += blockDim.x) sw.b3a[0][i] = b3_00[i];
        for (int i = t; i < 4;    i += blockDim.x) sw.b3a[1][i] = b3_01[i];
        for (int i = t; i < 4;    i += blockDim.x) sw.b3a[2][i] = b3_10[i];
        for (int i = t; i < 192;  i += blockDim.x) ((float*)sw.W3_11)[i] = W3_11[i];
        for (int i = t; i < 12;   i += blockDim.x) sw.b3_11[i] = b3_11[i];
        for (int i = t; i < 8;    i += blockDim.x) sw.wq[i] = wq[i];
    }
    __syncthreads();

    int e = blockIdx.x * blockDim.x + threadIdx.x;
    if (e >= N_EDGES) return;

    int uu = u[e], vv = v[e];
    float f0u0 = f0[2 * uu], f0u1 = f0[2 * uu + 1];
    float f0v0 = f0[2 * vv], f0v1 = f0[2 * vv + 1];
    float f1vv[6];
#pragma unroll
    for (int i = 0; i < 6; i++) f1vv[i] = f1[6 * vv + i];

    float v0 = f0u0 * f0v0;
    float v1 = f0u1 * f0v1;
    float v2 = dist[e];

    float R[12];

    // (l=0,k=0)  i=0
    radial<4>(sw, 0, (const float*)sw.W3a[0], sw.b3a[0], v0, v1, v2, R);
    float wj00e = wj00[e];
    float k0_0 = wj00e * fmaf(R[0], f0v0, R[1] * f0v1);
    float k0_1 = wj00e * fmaf(R[2], f0v0, R[3] * f0v1);

    // (l=0,k=1)  i=1
    radial<4>(sw, 1, (const float*)sw.W3a[1], sw.b3a[1], v0, v1, v2, R);
    {
        float w0 = wj01[3 * e + 0], w1 = wj01[3 * e + 1], w2 = wj01[3 * e + 2];
        float t0 = fmaf(w0, f1vv[0], fmaf(w1, f1vv[1], w2 * f1vv[2]));
        float t1 = fmaf(w0, f1vv[3], fmaf(w1, f1vv[4], w2 * f1vv[5]));
        k0_0 = fmaf(R[0], t0, fmaf(R[1], t1, k0_0));
        k0_1 = fmaf(R[2], t0, fmaf(R[3], t1, k0_1));
    }

    // (l=1,k=0)  i=2
    float k1[2][3];
    radial<4>(sw, 2, (const float*)sw.W3a[2], sw.b3a[2], v0, v1, v2, R);
    {
        float d0 = fmaf(R[0], f0v0, R[1] * f0v1);
        float d1 = fmaf(R[2], f0v0, R[3] * f0v1);
#pragma unroll
        for (int l = 0; l < 3; l++) {
            float w = wj10[3 * e + l];
            k1[0][l] = d0 * w;
            k1[1][l] = d1 * w;
        }
    }

    // (l=1,k=1)  i=3 : R reshaped [3(j)][2(o)][2(i)], wj11 [3(j)][3(l)][3(kk)]
    radial<12>(sw, 3, (const float*)sw.W3_11, sw.b3_11, v0, v1, v2, R);
#pragma unroll
    for (int j = 0; j < 3; j++) {
        float w[9];
#pragma unroll
        for (int x = 0; x < 9; x++) w[x] = wj11[27 * e + 9 * j + x];
#pragma unroll
        for (int l = 0; l < 3; l++) {
            float s0 = fmaf(w[3 * l], f1vv[0], fmaf(w[3 * l + 1], f1vv[1], w[3 * l + 2] * f1vv[2]));
            float s1 = fmaf(w[3 * l], f1vv[3], fmaf(w[3 * l + 1], f1vv[4], w[3 * l + 2] * f1vv[5]));
            k1[0][l] = fmaf(R[4 * j + 0], s0, fmaf(R[4 * j + 1], s1, k1[0][l]));
            k1[1][l] = fmaf(R[4 * j + 2], s0, fmaf(R[4 * j + 3], s1, k1[1][l]));
        }
    }

    // q[v] and dot
    // wq linear index [p][o][i] = p*4 + o*2 + i
    float dot = 0.f;
#pragma unroll
    for (int o = 0; o < 2; o++) {
        float q0 = fmaf(sw.wq[o * 2 + 0], f0v0, sw.wq[o * 2 + 1] * f0v1);
        dot = fmaf(q0, (o == 0 ? k0_0 : k0_1), dot);
#pragma unroll
        for (int m = 0; m < 3; m++) {
            float q1 = fmaf(sw.wq[4 + o * 2 + 0], f1vv[m], sw.wq[4 + o * 2 + 1] * f1vv[3 + m]);
            dot = fmaf(q1, k1[o][m], dot);
        }
    }

    g_dot[e] = dot;
    atomicMaxF(&g_m[vv], dot);
}

__global__ void exp_kernel(const int* __restrict__ v, float* __restrict__ out) {
    int e = blockIdx.x * blockDim.x + threadIdx.x;
    if (e >= N_EDGES) return;
    int vv = v[e];
    float p = expf(g_dot[e] - g_m[vv]);
    out[e] = p;
    atomicAdd(&g_s[vv], p);
}

__global__ void norm_kernel(const int* __restrict__ v, float* __restrict__ out) {
    int e = blockIdx.x * blockDim.x + threadIdx.x;
    if (e >= N_EDGES) return;
    out[e] = out[e] / g_s[v[e]];
}

extern "C" void kernel_launch(void* const* d_in, const int* in_sizes, int n_in,
                              void* d_out, int out_size) {
    const float* f0    = (const float*)d_in[0];
    const float* f1    = (const float*)d_in[1];
    const float* dist  = (const float*)d_in[2];
    const int*   u     = (const int*)d_in[3];
    const int*   v     = (const int*)d_in[4];
    const float* wq    = (const float*)d_in[5];
    const float* wj00  = (const float*)d_in[6];
    const float* wj01  = (const float*)d_in[7];
    const float* wj10  = (const float*)d_in[8];
    const float* wj11  = (const float*)d_in[9];
    const float* rW1   = (const float*)d_in[10];
    const float* rb1   = (const float*)d_in[11];
    const float* g1    = (const float*)d_in[12];
    const float* be1   = (const float*)d_in[13];
    const float* rW2   = (const float*)d_in[14];
    const float* rb2   = (const float*)d_in[15];
    const float* g2    = (const float*)d_in[16];
    const float* be2   = (const float*)d_in[17];
    const float* W3_00 = (const float*)d_in[18];
    const float* b3_00 = (const float*)d_in[19];
    const float* W3_01 = (const float*)d_in[20];
    const float* b3_01 = (const float*)d_in[21];
    const float* W3_10 = (const float*)d_in[22];
    const float* b3_10 = (const float*)d_in[23];
    const float* W3_11 = (const float*)d_in[24];
    const float* b3_11 = (const float*)d_in[25];
    float* out = (float*)d_out;

    init_kernel<<<(N_NODES + 255) / 256, 256>>>();
    edge_kernel<<<(N_EDGES + 255) / 256, 256>>>(
        f0, f1, dist, u, v, wq, wj00, wj01, wj10, wj11,
        rW1, rb1, g1, be1, rW2, rb2, g2, be2,
        W3_00, b3_00, W3_01, b3_01, W3_10, b3_10, W3_11, b3_11);
    exp_kernel<<<(N_EDGES + 255) / 256, 256>>>(v, out);
    norm_kernel<<<(N_EDGES + 255) / 256, 256>>>(v, out);
}